// round 14
// baseline (speedup 1.0000x reference)
#include <cuda_runtime.h>
#include <cuda_bf16.h>
#include <cstdint>

#define B_ 64
#define A_ 512
#define D_ 256
#define H_ 8
#define DH_ 32
#define F_ 512
#define ROWS_ (B_*A_)            // 32768
#define SZ_ ((size_t)ROWS_*D_)   // floats per [B,A,D] buffer

// Scratch: q,k,v,o,proj,h,h2 (7 x [B,A,D]) + pooled + fc1 + fc2
__device__ float g_scratch[7*8388608 + B_*D_ + 2*B_*F_];

// ===========================================================================
// mma.sync bf16 split-precision GEMM (baseline PTX, works on compute_103)
// C[M,N] = A[M,K] @ W[K,N] + bias  (optional relu)
// CTA tile 128x128, K staged in chunks of 128.
// A,B split into (hi,lo) bf16; 3 MMA terms: hi*hi + hi*lo + lo*hi (fp32 acc).
// SMEM: row-linear, 272-byte row stride (256 data + 16 pad) -> conflict-free
// fragment loads (word bank = 4*group + threadInGroup).
// ===========================================================================
#define GS_ROWB 272                       // bytes per smem row (128 bf16 + pad)
#define GS_AHI 0
#define GS_ALO (GS_AHI + 128*GS_ROWB)     // 34816
#define GS_BHI (GS_ALO + 128*GS_ROWB)
#define GS_BLO (GS_BHI + 128*GS_ROWB)
#define GS_SMEM (GS_BLO + 128*GS_ROWB)    // 139264 bytes

static __device__ __forceinline__ void split_bf16(float x, unsigned short& h,
                                                  unsigned short& l) {
  __nv_bfloat16 hb = __float2bfloat16(x);
  h = __bfloat16_as_ushort(hb);
  l = __bfloat16_as_ushort(__float2bfloat16(x - __bfloat162float(hb)));
}

__device__ __forceinline__ void mma16816(float* d, const uint32_t* a,
                                         uint32_t b0, uint32_t b1) {
  asm volatile(
      "mma.sync.aligned.m16n8k16.row.col.f32.bf16.bf16.f32 "
      "{%0,%1,%2,%3}, {%4,%5,%6,%7}, {%8,%9}, {%0,%1,%2,%3};"
      : "+f"(d[0]), "+f"(d[1]), "+f"(d[2]), "+f"(d[3])
      : "r"(a[0]), "r"(a[1]), "r"(a[2]), "r"(a[3]), "r"(b0), "r"(b1));
}

__global__ __launch_bounds__(256) void gemm_mma_kernel(
    const float* __restrict__ A, const float* __restrict__ W,
    const float* __restrict__ bias, float* __restrict__ C,
    int M, int N, int K, int relu)
{
  extern __shared__ char sm[];
  const int tid = threadIdx.x;
  const int wid = tid >> 5;
  const int lane = tid & 31;
  const int g = lane >> 2;          // groupID 0..7
  const int tg = lane & 3;          // threadInGroup 0..3
  const int bm = blockIdx.y * 128;
  const int bn = blockIdx.x * 128;
  const int wm = (wid >> 1) * 32;   // warp m-offset within tile (4 warps)
  const int wn = (wid & 1) * 64;    // warp n-offset within tile (2 warps)

  float acc[2][8][4];
  #pragma unroll
  for (int i = 0; i < 2; i++)
    #pragma unroll
    for (int j = 0; j < 8; j++)
      #pragma unroll
      for (int c = 0; c < 4; c++) acc[i][j][c] = 0.f;

  const int nchunks = K >> 7;
  for (int kc = 0; kc < nchunks; kc++) {
    const int k0 = kc << 7;
    // ---- stage A chunk [128 rows x 128 k] fp32 -> (hi,lo) bf16 ----
    for (int it = tid; it < 128 * 32; it += 256) {
      int row = it >> 5;
      int k4 = (it & 31) << 2;
      float4 v = make_float4(0.f, 0.f, 0.f, 0.f);
      int grow = bm + row;
      if (grow < M) v = *(const float4*)(A + (size_t)grow * K + k0 + k4);
      unsigned short h0, h1, h2, h3, l0, l1, l2, l3;
      split_bf16(v.x, h0, l0); split_bf16(v.y, h1, l1);
      split_bf16(v.z, h2, l2); split_bf16(v.w, h3, l3);
      uint32_t off = (uint32_t)(row * GS_ROWB + k4 * 2);
      *(uint2*)(sm + GS_AHI + off) =
          make_uint2((uint32_t)h0 | ((uint32_t)h1 << 16),
                     (uint32_t)h2 | ((uint32_t)h3 << 16));
      *(uint2*)(sm + GS_ALO + off) =
          make_uint2((uint32_t)l0 | ((uint32_t)l1 << 16),
                     (uint32_t)l2 | ((uint32_t)l3 << 16));
    }
    // ---- stage B chunk: W[k][n] -> Bs[n][k] (transposed), (hi,lo) ----
    for (int it = tid; it < 128 * 32; it += 256) {
      int k = it >> 5;
      int n4 = (it & 31) << 2;
      float4 v = *(const float4*)(W + (size_t)(k0 + k) * N + bn + n4);
      float vv[4] = {v.x, v.y, v.z, v.w};
      #pragma unroll
      for (int j = 0; j < 4; j++) {
        unsigned short h, l;
        split_bf16(vv[j], h, l);
        uint32_t off = (uint32_t)((n4 + j) * GS_ROWB + k * 2);
        *(unsigned short*)(sm + GS_BHI + off) = h;
        *(unsigned short*)(sm + GS_BLO + off) = l;
      }
    }
    __syncthreads();

    // ---- compute: 8 ksteps of 16 ----
    #pragma unroll
    for (int ks = 0; ks < 8; ks++) {
      const int kb = ks * 16;
      // A fragments (hi & lo) for 2 m-tiles
      uint32_t ahi[2][4], alo[2][4];
      #pragma unroll
      for (int i = 0; i < 2; i++) {
        int r0 = wm + i * 16 + g;
        uint32_t o00 = (uint32_t)(r0 * GS_ROWB + (kb + tg * 2) * 2);
        uint32_t o10 = (uint32_t)((r0 + 8) * GS_ROWB + (kb + tg * 2) * 2);
        ahi[i][0] = *(const uint32_t*)(sm + GS_AHI + o00);
        ahi[i][1] = *(const uint32_t*)(sm + GS_AHI + o10);
        ahi[i][2] = *(const uint32_t*)(sm + GS_AHI + o00 + 16);
        ahi[i][3] = *(const uint32_t*)(sm + GS_AHI + o10 + 16);
        alo[i][0] = *(const uint32_t*)(sm + GS_ALO + o00);
        alo[i][1] = *(const uint32_t*)(sm + GS_ALO + o10);
        alo[i][2] = *(const uint32_t*)(sm + GS_ALO + o00 + 16);
        alo[i][3] = *(const uint32_t*)(sm + GS_ALO + o10 + 16);
      }
      #pragma unroll
      for (int j = 0; j < 8; j++) {
        int col = wn + j * 8 + g;
        uint32_t ob = (uint32_t)(col * GS_ROWB + (kb + tg * 2) * 2);
        uint32_t bh0 = *(const uint32_t*)(sm + GS_BHI + ob);
        uint32_t bh1 = *(const uint32_t*)(sm + GS_BHI + ob + 16);
        uint32_t bl0 = *(const uint32_t*)(sm + GS_BLO + ob);
        uint32_t bl1 = *(const uint32_t*)(sm + GS_BLO + ob + 16);
        #pragma unroll
        for (int i = 0; i < 2; i++) {
          mma16816(acc[i][j], ahi[i], bh0, bh1);   // hi*hi
          mma16816(acc[i][j], ahi[i], bl0, bl1);   // hi*lo
          mma16816(acc[i][j], alo[i], bh0, bh1);   // lo*hi
        }
      }
    }
    __syncthreads();
  }

  // ---- epilogue: fragment -> gmem with bias (+relu) ----
  #pragma unroll
  for (int i = 0; i < 2; i++) {
    #pragma unroll
    for (int j = 0; j < 8; j++) {
      int col = bn + wn + j * 8 + tg * 2;
      float b0 = bias[col], b1 = bias[col + 1];
      int r0 = bm + wm + i * 16 + g;
      float o0 = acc[i][j][0] + b0;
      float o1 = acc[i][j][1] + b1;
      float o2 = acc[i][j][2] + b0;
      float o3 = acc[i][j][3] + b1;
      if (relu) {
        o0 = fmaxf(o0, 0.f); o1 = fmaxf(o1, 0.f);
        o2 = fmaxf(o2, 0.f); o3 = fmaxf(o3, 0.f);
      }
      if (r0 < M) *(float2*)(C + (size_t)r0 * N + col) = make_float2(o0, o1);
      if (r0 + 8 < M) *(float2*)(C + (size_t)(r0 + 8) * N + col) = make_float2(o2, o3);
    }
  }
}

// ---------------------------------------------------------------------------
// Attention: one CTA per (b,h). K^T, V^T in smem (stride 513, conflict-free).
// ---------------------------------------------------------------------------
#define KT_STRIDE 513
__global__ __launch_bounds__(256) void attn_kernel(
    const float* __restrict__ Q, const float* __restrict__ K,
    const float* __restrict__ V, float* __restrict__ O)
{
  extern __shared__ float smf[];
  float* Kt = smf;
  float* Vt = smf + 32 * KT_STRIDE;
  const int b = blockIdx.x >> 3;
  const int h = blockIdx.x & 7;
  const int tid = threadIdx.x;
  const int lane = tid & 31;
  const int w = tid >> 5;

  const float* Kb = K + ((size_t)b * A_) * D_ + h * DH_;
  const float* Vb = V + ((size_t)b * A_) * D_ + h * DH_;
  for (int idx = tid; idx < A_ * 8; idx += 256) {
    int kk = idx >> 3;
    int d4 = (idx & 7) << 2;
    float4 kv = *(const float4*)(Kb + (size_t)kk * D_ + d4);
    float4 vv = *(const float4*)(Vb + (size_t)kk * D_ + d4);
    Kt[(d4 + 0) * KT_STRIDE + kk] = kv.x;
    Kt[(d4 + 1) * KT_STRIDE + kk] = kv.y;
    Kt[(d4 + 2) * KT_STRIDE + kk] = kv.z;
    Kt[(d4 + 3) * KT_STRIDE + kk] = kv.w;
    Vt[(d4 + 0) * KT_STRIDE + kk] = vv.x;
    Vt[(d4 + 1) * KT_STRIDE + kk] = vv.y;
    Vt[(d4 + 2) * KT_STRIDE + kk] = vv.z;
    Vt[(d4 + 3) * KT_STRIDE + kk] = vv.w;
  }
  __syncthreads();

  const float scale = 0.17677669529663687f;
  const float* Qb = Q + ((size_t)b * A_) * D_ + h * DH_ + lane;
  float* Ob = O + ((size_t)b * A_) * D_ + h * DH_ + lane;

  for (int g = 0; g < 16; g++) {
    const int q0 = w * 64 + g * 4;
    float qreg[4];
    float sc[4][16];
    #pragma unroll
    for (int m = 0; m < 4; m++) {
      qreg[m] = Qb[(size_t)(q0 + m) * D_] * scale;
      #pragma unroll
      for (int i = 0; i < 16; i++) sc[m][i] = 0.f;
    }
    for (int d = 0; d < 32; d++) {
      float qv0 = __shfl_sync(0xffffffffu, qreg[0], d);
      float qv1 = __shfl_sync(0xffffffffu, qreg[1], d);
      float qv2 = __shfl_sync(0xffffffffu, qreg[2], d);
      float qv3 = __shfl_sync(0xffffffffu, qreg[3], d);
      const float* kr = &Kt[d * KT_STRIDE + lane];
      #pragma unroll
      for (int i = 0; i < 16; i++) {
        float kv = kr[i * 32];
        sc[0][i] += qv0 * kv;
        sc[1][i] += qv1 * kv;
        sc[2][i] += qv2 * kv;
        sc[3][i] += qv3 * kv;
      }
    }
    float acc[4];
    #pragma unroll
    for (int m = 0; m < 4; m++) {
      float mx = sc[m][0];
      #pragma unroll
      for (int i = 1; i < 16; i++) mx = fmaxf(mx, sc[m][i]);
      #pragma unroll
      for (int o = 16; o; o >>= 1) mx = fmaxf(mx, __shfl_xor_sync(0xffffffffu, mx, o));
      float s = 0.f;
      #pragma unroll
      for (int i = 0; i < 16; i++) {
        float e = __expf(sc[m][i] - mx);
        sc[m][i] = e;
        s += e;
      }
      #pragma unroll
      for (int o = 16; o; o >>= 1) s += __shfl_xor_sync(0xffffffffu, s, o);
      float inv = 1.f / s;
      #pragma unroll
      for (int i = 0; i < 16; i++) sc[m][i] *= inv;
      acc[m] = 0.f;
    }
    const float* vr = &Vt[lane * KT_STRIDE];
    #pragma unroll
    for (int i = 0; i < 16; i++) {
      for (int j = 0; j < 32; j++) {
        float vv = vr[i * 32 + j];
        acc[0] += __shfl_sync(0xffffffffu, sc[0][i], j) * vv;
        acc[1] += __shfl_sync(0xffffffffu, sc[1][i], j) * vv;
        acc[2] += __shfl_sync(0xffffffffu, sc[2][i], j) * vv;
        acc[3] += __shfl_sync(0xffffffffu, sc[3][i], j) * vv;
      }
    }
    #pragma unroll
    for (int m = 0; m < 4; m++) Ob[(size_t)(q0 + m) * D_] = acc[m];
  }
}

// ---------------------------------------------------------------------------
// LayerNorm(res + x) * g + b, warp per row of 256.
// ---------------------------------------------------------------------------
__global__ __launch_bounds__(256) void ln_residual_kernel(
    const float* __restrict__ res, const float* __restrict__ x,
    const float* __restrict__ g, const float* __restrict__ bta,
    float* __restrict__ out)
{
  const int gw = (blockIdx.x * 256 + threadIdx.x) >> 5;
  const int lane = threadIdx.x & 31;
  const float* r = res + (size_t)gw * D_;
  const float* xx = x + (size_t)gw * D_;
  float v[8];
  float s = 0.f;
  #pragma unroll
  for (int i = 0; i < 8; i++) {
    v[i] = r[lane + i * 32] + xx[lane + i * 32];
    s += v[i];
  }
  #pragma unroll
  for (int o = 16; o; o >>= 1) s += __shfl_xor_sync(0xffffffffu, s, o);
  float mu = s * (1.f / 256.f);
  float vs = 0.f;
  #pragma unroll
  for (int i = 0; i < 8; i++) { float d = v[i] - mu; vs += d * d; }
  #pragma unroll
  for (int o = 16; o; o >>= 1) vs += __shfl_xor_sync(0xffffffffu, vs, o);
  float inv = rsqrtf(vs * (1.f / 256.f) + 1e-5f);
  float* op = out + (size_t)gw * D_;
  #pragma unroll
  for (int i = 0; i < 8; i++)
    op[lane + i * 32] = (v[i] - mu) * inv * g[lane + i * 32] + bta[lane + i * 32];
}

// ---------------------------------------------------------------------------
// Pooling: w = softmax_a(||h[b,a,:]||); pooled[b,d] = sum_a w_a h[b,a,d]
// ---------------------------------------------------------------------------
__global__ __launch_bounds__(256) void pool_kernel(
    const float* __restrict__ h, float* __restrict__ pooled)
{
  __shared__ float wsm[A_];
  __shared__ float rbuf[8];
  const int b = blockIdx.x;
  const int tid = threadIdx.x;
  const int lane = tid & 31;
  const int w = tid >> 5;
  const float* hb = h + (size_t)b * A_ * D_;

  for (int a = w; a < A_; a += 8) {
    float s = 0.f;
    #pragma unroll
    for (int i = 0; i < 8; i++) {
      float v = hb[(size_t)a * D_ + lane + i * 32];
      s += v * v;
    }
    #pragma unroll
    for (int o = 16; o; o >>= 1) s += __shfl_xor_sync(0xffffffffu, s, o);
    if (lane == 0) wsm[a] = sqrtf(s);
  }
  __syncthreads();

  float lm = -1e30f;
  for (int a = tid; a < A_; a += 256) lm = fmaxf(lm, wsm[a]);
  #pragma unroll
  for (int o = 16; o; o >>= 1) lm = fmaxf(lm, __shfl_xor_sync(0xffffffffu, lm, o));
  if (lane == 0) rbuf[w] = lm;
  __syncthreads();
  float mx = rbuf[0];
  #pragma unroll
  for (int i = 1; i < 8; i++) mx = fmaxf(mx, rbuf[i]);
  __syncthreads();

  float ls = 0.f;
  for (int a = tid; a < A_; a += 256) {
    float e = __expf(wsm[a] - mx);
    wsm[a] = e;
    ls += e;
  }
  #pragma unroll
  for (int o = 16; o; o >>= 1) ls += __shfl_xor_sync(0xffffffffu, ls, o);
  if (lane == 0) rbuf[w] = ls;
  __syncthreads();
  float tot = 0.f;
  #pragma unroll
  for (int i = 0; i < 8; i++) tot += rbuf[i];
  float inv = 1.f / tot;

  const int d = tid;
  float accd = 0.f;
  for (int a = 0; a < A_; a++) accd += wsm[a] * hb[(size_t)a * D_ + d];
  pooled[(size_t)b * D_ + d] = accd * inv;
}

// ---------------------------------------------------------------------------
// Final head: out[64,2] = h2 @ W_out + b_out
// ---------------------------------------------------------------------------
__global__ void fcout_kernel(const float* __restrict__ h2,
                             const float* __restrict__ Wo,
                             const float* __restrict__ bo,
                             float* __restrict__ out)
{
  int idx = threadIdx.x;
  if (idx >= B_ * 2) return;
  int m = idx >> 1, n = idx & 1;
  float acc = bo[n];
  for (int k = 0; k < F_; k++) acc += h2[(size_t)m * F_ + k] * Wo[k * 2 + n];
  out[idx] = acc;
}

// ---------------------------------------------------------------------------
extern "C" void kernel_launch(void* const* d_in, const int* in_sizes, int n_in,
                              void* d_out, int out_size)
{
  const float* trg   = (const float*)d_in[0];
  const float* src   = (const float*)d_in[1];
  const float* W_sa  = (const float*)d_in[2];
  const float* b_sa  = (const float*)d_in[3];
  const float* W_ea  = (const float*)d_in[4];
  const float* b_ea  = (const float*)d_in[5];
  const float* ln_g  = (const float*)d_in[6];
  const float* ln_b  = (const float*)d_in[7];
  const float* W_fc1 = (const float*)d_in[8];
  const float* b_fc1 = (const float*)d_in[9];
  const float* W_fc2 = (const float*)d_in[10];
  const float* b_fc2 = (const float*)d_in[11];
  const float* W_out = (const float*)d_in[12];
  const float* b_out = (const float*)d_in[13];
  float* outp = (float*)d_out;

  float* base = nullptr;
  cudaGetSymbolAddress((void**)&base, g_scratch);
  float* gq    = base;
  float* gk    = base + SZ_;
  float* gv    = base + 2 * SZ_;
  float* go    = base + 3 * SZ_;
  float* gp    = base + 4 * SZ_;
  float* gh    = base + 5 * SZ_;
  float* gh2   = base + 6 * SZ_;
  float* gpool = base + 7 * SZ_;
  float* gfc1  = gpool + B_ * D_;
  float* gfc2  = gfc1 + B_ * F_;

  const int smem_attn = 2 * 32 * KT_STRIDE * (int)sizeof(float);
  cudaFuncSetAttribute((const void*)attn_kernel,
                       cudaFuncAttributeMaxDynamicSharedMemorySize, smem_attn);
  cudaFuncSetAttribute((const void*)gemm_mma_kernel,
                       cudaFuncAttributeMaxDynamicSharedMemorySize, GS_SMEM);

  dim3 gP(2, 256);   // projections: [32768,256] = 2 col tiles x 256 row tiles

  // ---- self-attention block ----
  gemm_mma_kernel<<<gP, 256, GS_SMEM>>>(trg, W_sa,          b_sa,       gq, ROWS_, D_, D_, 0);
  gemm_mma_kernel<<<gP, 256, GS_SMEM>>>(trg, W_sa + 65536,  b_sa + 256, gk, ROWS_, D_, D_, 0);
  gemm_mma_kernel<<<gP, 256, GS_SMEM>>>(trg, W_sa + 131072, b_sa + 512, gv, ROWS_, D_, D_, 0);
  attn_kernel<<<B_ * H_, 256, smem_attn>>>(gq, gk, gv, go);
  gemm_mma_kernel<<<gP, 256, GS_SMEM>>>(go, W_sa + 196608,  b_sa + 768, gp, ROWS_, D_, D_, 0);
  ln_residual_kernel<<<ROWS_ / 8, 256>>>(trg, gp, ln_g, ln_b, gh);

  // ---- cross-attention block ----
  gemm_mma_kernel<<<gP, 256, GS_SMEM>>>(gh,  W_ea,          b_ea,       gq, ROWS_, D_, D_, 0);
  gemm_mma_kernel<<<gP, 256, GS_SMEM>>>(src, W_ea + 65536,  b_ea + 256, gk, ROWS_, D_, D_, 0);
  gemm_mma_kernel<<<gP, 256, GS_SMEM>>>(src, W_ea + 131072, b_ea + 512, gv, ROWS_, D_, D_, 0);
  attn_kernel<<<B_ * H_, 256, smem_attn>>>(gq, gk, gv, go);
  gemm_mma_kernel<<<gP, 256, GS_SMEM>>>(go, W_ea + 196608,  b_ea + 768, gp, ROWS_, D_, D_, 0);
  ln_residual_kernel<<<ROWS_ / 8, 256>>>(gh, gp, ln_g, ln_b, gh2);

  // ---- pooling + head ----
  pool_kernel<<<B_, 256>>>(gh2, gpool);
  gemm_mma_kernel<<<dim3(4, 1), 256, GS_SMEM>>>(gpool, W_fc1, b_fc1, gfc1, B_, F_, D_, 1);
  gemm_mma_kernel<<<dim3(4, 1), 256, GS_SMEM>>>(gfc1,  W_fc2, b_fc2, gfc2, B_, F_, F_, 1);
  fcout_kernel<<<1, 128>>>(gfc2, W_out, b_out, outp);
}